// round 4
// baseline (speedup 1.0000x reference)
#include <cuda_runtime.h>
#include <math.h>

typedef unsigned long long ull;

// Problem constants
#define B    512
#define IU   8
#define C    1152
#define J    10
#define S    16
#define NR   3
#define R    (B*IU)      // 4096

// Tiling
#define CCB  8           // c's per block (owned exclusively)
#define NCB  (C/CCB)     // 144 blocks
#define BT   128         // b's per tile
#define NBT  (B/BT)      // 4 tiles
#define NTHR 512
#define WJS  72          // smem ull-stride per (c,j) row (padded from 64)
#define RSPLIT 8         // k_rs1 split factor

// Scratch (__device__ globals; no allocation)
__device__ __align__(16) ull  g_xd[(size_t)C*B*IU];   // duplicated x (x,x)  37.7MB
__device__ __align__(16) ull  g_Wp[(size_t)C*J*64];   // packed W (s,s+8)    5.9MB
__device__ float g_b[C*J];
__device__ __align__(16) ull  g_sp2[NCB][(size_t)J*B*8];     // s partials 47MB
__device__ __align__(16) ull  g_spp[RSPLIT][(size_t)J*B*8];  // split-k stage
__device__ __align__(16) ull  g_v2[(size_t)J*B*8];           // packed v

struct SMem {
    ull   Wp[CCB*J*WJS];      // 46080 B
    ull   xd[2][CCB*BT*IU];   // 131072 B (double buffer)
    float dsm[16][CCB*J];     // 5120 B  per-warp delta partials
    float bn[CCB*J];
    float ccs[CCB*J];
};

// ---- packed f32x2 helpers ------------------------------------------------
__device__ __forceinline__ void fma2(ull& d, ull a, ull b) {
    asm("fma.rn.f32x2 %0, %1, %2, %0;" : "+l"(d) : "l"(a), "l"(b));
}
__device__ __forceinline__ ull add2(ull a, ull b) {
    ull d; asm("add.rn.f32x2 %0, %1, %2;" : "=l"(d) : "l"(a), "l"(b)); return d;
}
__device__ __forceinline__ ull pack2(float lo, float hi) {
    return ((ull)__float_as_uint(hi) << 32) | (ull)__float_as_uint(lo);
}
__device__ __forceinline__ ull dup2(float f) {
    unsigned u = __float_as_uint(f); return ((ull)u << 32) | (ull)u;
}
__device__ __forceinline__ float lo2(ull v) { return __uint_as_float((unsigned)v); }
__device__ __forceinline__ float hi2(ull v) { return __uint_as_float((unsigned)(v >> 32)); }

// ---- cp.async helpers ----------------------------------------------------
__device__ __forceinline__ void cpa16(void* dst, const void* src) {
    unsigned s = (unsigned)__cvta_generic_to_shared(dst);
    asm volatile("cp.async.cg.shared.global [%0], [%1], 16;" :: "r"(s), "l"(src));
}
__device__ __forceinline__ void cpcommit() {
    asm volatile("cp.async.commit_group;" ::: "memory");
}
template <int N> __device__ __forceinline__ void cpwait() {
    asm volatile("cp.async.wait_group %0;" :: "n"(N) : "memory");
}

// ---------------------------------------------------------------------------
// Prep: x[b][i][c] -> g_xd[c][b*8+i] duplicated (x,x)
// ---------------------------------------------------------------------------
__global__ void k_transpose(const float* __restrict__ x) {
    __shared__ float t[32][33];
    int cb = blockIdx.x * 32, rb = blockIdx.y * 32;
    int tx = threadIdx.x, ty = threadIdx.y;
    #pragma unroll
    for (int k = 0; k < 32; k += 8)
        t[ty + k][tx] = x[(size_t)(rb + ty + k) * C + cb + tx];
    __syncthreads();
    #pragma unroll
    for (int k = 0; k < 32; k += 8)
        g_xd[(size_t)(cb + ty + k) * R + rb + tx] = dup2(t[tx][ty + k]);
}

// Prep: W[c][j][s][i] -> g_Wp[cj][ih*32 + il*8 + sh] = (W[..sh..i], W[..sh+8..i])
__global__ void k_prepW(const float* __restrict__ W) {
    int gid = blockIdx.x * 256 + threadIdx.x;
    if (gid >= C * J * 64) return;
    int sh = gid & 7, il = (gid >> 3) & 3, ih = (gid >> 5) & 1, cj = gid >> 6;
    int i = ih * 4 + il;
    float lo = W[((size_t)cj * 16 + sh) * 8 + i];
    float hi = W[((size_t)cj * 16 + sh + 8) * 8 + i];
    g_Wp[(size_t)cj * 64 + ih * 32 + il * 8 + sh] = pack2(lo, hi);
}

// ---------------------------------------------------------------------------
// cp.async stagers
// ---------------------------------------------------------------------------
__device__ __forceinline__ void issue_W(ull* Wp, int c0, int tid) {
    const ull* src = g_Wp + (size_t)c0 * J * 64;
    #pragma unroll
    for (int t = tid; t < CCB * J * 32; t += NTHR) {
        int row = t >> 5, ch = t & 31;
        cpa16(Wp + row * WJS + ch * 2, src + row * 64 + ch * 2);
    }
}
__device__ __forceinline__ void issue_x(ull* xd, int c0, int b0, int tid) {
    #pragma unroll
    for (int t = tid; t < CCB * BT * IU / 2; t += NTHR) {
        int cl = t >> 9, ch = t & 511;
        cpa16(xd + cl * (BT * IU) + ch * 2,
              g_xd + (size_t)(c0 + cl) * R + (size_t)b0 * IU + ch * 2);
    }
}

// ---------------------------------------------------------------------------
// Fused routing kernel. MODE 0: first iteration (no delta sweep, W unscaled,
// cc=0.1 folded as postscale downstream, zero-init g_b).
// MODE 1: delta sweep -> b update -> softmax -> rescale Wp in smem -> s sweep.
// Block owns c's [c0, c0+8) exclusively; covers all 512 b in 4 tiles.
// ---------------------------------------------------------------------------
template <int MODE>
__global__ void __launch_bounds__(NTHR, 1) k_fused() {
    extern __shared__ char smraw[];
    SMem& sm = *(SMem*)smraw;
    int tid = threadIdx.x;
    int c0  = blockIdx.x * CCB;
    int sh  = tid & 7;
    int jb  = ((tid >> 3) & 1) * 5;
    int bt4 = tid >> 4;          // 0..31: b-quad within tile
    int warp = tid >> 5, lane = tid & 31;

    issue_W(sm.Wp, c0, tid);
    issue_x(sm.xd[0], c0, 0, tid);
    cpcommit();

    if (MODE == 0) {
        if (tid < CCB * J) g_b[c0 * J + tid] = 0.f;
    } else {
        #pragma unroll
        for (int t = tid; t < 16 * CCB * J; t += NTHR) ((float*)sm.dsm)[t] = 0.f;
    }

    if (MODE == 1) {
        // ---- sweep 1: delta_b ----
        #pragma unroll
        for (int bt = 0; bt < NBT; bt++) {
            if (bt + 1 < NBT) { issue_x(sm.xd[(bt + 1) & 1], c0, (bt + 1) * BT, tid); cpcommit(); }
            ull vv[5][4];
            #pragma unroll
            for (int jj = 0; jj < 5; jj++)
                #pragma unroll
                for (int t = 0; t < 4; t++)
                    vv[jj][t] = g_v2[((size_t)(jb + jj) * B + bt * BT + bt4 * 4 + t) * 8 + sh];
            if (bt + 1 < NBT) cpwait<1>(); else cpwait<0>();
            __syncthreads();
            const ull* xd = sm.xd[bt & 1];
            #pragma unroll 1
            for (int cl = 0; cl < CCB; cl++) {
                ull p2[5] = {0, 0, 0, 0, 0};
                const ull* xrow = xd + (cl * BT + bt4 * 4) * IU;
                #pragma unroll
                for (int ih = 0; ih < 2; ih++) {
                    ulonglong2 xA[4], xB[4];
                    #pragma unroll
                    for (int t = 0; t < 4; t++) {
                        const ulonglong2* xp = (const ulonglong2*)(xrow + t * IU + ih * 4);
                        xA[t] = xp[0]; xB[t] = xp[1];
                    }
                    const ull* wb_ = sm.Wp + (cl * J + jb) * WJS + ih * 32 + sh;
                    #pragma unroll
                    for (int jj = 0; jj < 5; jj++) {
                        const ull* w = wb_ + jj * WJS;
                        ull y0 = 0, y1 = 0, y2 = 0, y3 = 0;
                        #pragma unroll
                        for (int t = 0; t < 4; t++) {
                            fma2(y0, vv[jj][t], xA[t].x);
                            fma2(y1, vv[jj][t], xA[t].y);
                            fma2(y2, vv[jj][t], xB[t].x);
                            fma2(y3, vv[jj][t], xB[t].y);
                        }
                        fma2(p2[jj], w[0],  y0);
                        fma2(p2[jj], w[8],  y1);
                        fma2(p2[jj], w[16], y2);
                        fma2(p2[jj], w[24], y3);
                    }
                }
                #pragma unroll
                for (int jj = 0; jj < 5; jj++) {
                    float p = lo2(p2[jj]) + hi2(p2[jj]);
                    p += __shfl_xor_sync(0xffffffffu, p, 1);
                    p += __shfl_xor_sync(0xffffffffu, p, 2);
                    p += __shfl_xor_sync(0xffffffffu, p, 4);
                    p += __shfl_xor_sync(0xffffffffu, p, 16);
                    if ((lane & 23) == 0)        // lanes 0 (jg0) and 8 (jg1)
                        sm.dsm[warp][cl * J + jb + jj] += p;
                }
            }
            __syncthreads();
        }
        // ---- b update + softmax (block-local, c's owned exclusively) ----
        if (tid < CCB * J) {
            float s = 0.f;
            #pragma unroll
            for (int w = 0; w < 16; w++) s += sm.dsm[w][tid];
            float nb = g_b[c0 * J + tid] + s * (1.f / B);
            g_b[c0 * J + tid] = nb;
            sm.bn[tid] = nb;
        }
        __syncthreads();
        if (tid < CCB) {
            float m = sm.bn[tid * J];
            #pragma unroll
            for (int j = 1; j < J; j++) m = fmaxf(m, sm.bn[tid * J + j]);
            float su = 0.f, e[J];
            #pragma unroll
            for (int j = 0; j < J; j++) { e[j] = expf(sm.bn[tid * J + j] - m); su += e[j]; }
            float inv = 1.f / su;
            #pragma unroll
            for (int j = 0; j < J; j++) sm.ccs[tid * J + j] = e[j] * inv;
        }
        __syncthreads();
        // ---- rescale Wp in place by cc ----
        #pragma unroll
        for (int t = tid; t < CCB * J * 64; t += NTHR) {
            int cj = t >> 6;
            float cv = sm.ccs[cj];
            ull w = sm.Wp[cj * WJS + (t & 63)];
            sm.Wp[cj * WJS + (t & 63)] = pack2(lo2(w) * cv, hi2(w) * cv);
        }
        __syncthreads();
        issue_x(sm.xd[0], c0, 0, tid);
        cpcommit();
    }

    // ---- sweep 2: s partials ----
    ull* spb = g_sp2[blockIdx.x];
    #pragma unroll
    for (int bt = 0; bt < NBT; bt++) {
        if (bt + 1 < NBT) { issue_x(sm.xd[(bt + 1) & 1], c0, (bt + 1) * BT, tid); cpcommit(); }
        if (bt + 1 < NBT) cpwait<1>(); else cpwait<0>();
        __syncthreads();
        const ull* xd = sm.xd[bt & 1];
        ull acc[5][4];
        #pragma unroll
        for (int jj = 0; jj < 5; jj++)
            #pragma unroll
            for (int t = 0; t < 4; t++) acc[jj][t] = 0ull;
        #pragma unroll
        for (int cl = 0; cl < CCB; cl++) {
            const ull* xrow = xd + (cl * BT + bt4 * 4) * IU;
            #pragma unroll
            for (int ih = 0; ih < 2; ih++) {
                ulonglong2 xA[4], xB[4];
                #pragma unroll
                for (int t = 0; t < 4; t++) {
                    const ulonglong2* xp = (const ulonglong2*)(xrow + t * IU + ih * 4);
                    xA[t] = xp[0]; xB[t] = xp[1];
                }
                const ull* wb_ = sm.Wp + (cl * J + jb) * WJS + ih * 32 + sh;
                #pragma unroll
                for (int jj = 0; jj < 5; jj++) {
                    const ull* w = wb_ + jj * WJS;
                    ull w0 = w[0], w1 = w[8], w2 = w[16], w3 = w[24];
                    #pragma unroll
                    for (int t = 0; t < 4; t++) {
                        fma2(acc[jj][t], w0, xA[t].x);
                        fma2(acc[jj][t], w1, xA[t].y);
                        fma2(acc[jj][t], w2, xB[t].x);
                        fma2(acc[jj][t], w3, xB[t].y);
                    }
                }
            }
        }
        #pragma unroll
        for (int jj = 0; jj < 5; jj++)
            #pragma unroll
            for (int t = 0; t < 4; t++)
                spb[((size_t)(jb + jj) * B + bt * BT + bt4 * 4 + t) * 8 + sh] = acc[jj][t];
        __syncthreads();
    }
}

// ---------------------------------------------------------------------------
// Split-k partial reduction: stage 1 sums 18 partials each (8-way split).
// ---------------------------------------------------------------------------
__global__ void k_rs1() {
    int idx = blockIdx.x * 256 + threadIdx.x;
    int p0 = blockIdx.y * (NCB / RSPLIT);
    ull a0 = 0ull, a1 = 0ull;
    #pragma unroll
    for (int p = 0; p < NCB / RSPLIT; p += 2) {
        a0 = add2(a0, g_sp2[p0 + p][idx]);
        a1 = add2(a1, g_sp2[p0 + p + 1][idx]);
    }
    g_spp[blockIdx.y][idx] = add2(a0, a1);
}

// Stage 2: sum splits, squash, write packed v (+ output on last iteration).
__global__ void k_rs2(float postscale, float* __restrict__ out) {
    int idx = blockIdx.x * 256 + threadIdx.x;
    ull a = g_spp[0][idx];
    #pragma unroll
    for (int p = 1; p < RSPLIT; p++) a = add2(a, g_spp[p][idx]);
    float lo = lo2(a) * postscale;
    float hi = hi2(a) * postscale;
    float m = lo * lo + hi * hi;
    m += __shfl_xor_sync(0xffffffffu, m, 1);
    m += __shfl_xor_sync(0xffffffffu, m, 2);
    m += __shfl_xor_sync(0xffffffffu, m, 4);
    float fac = sqrtf(m) / (1.f + m);
    float vlo = lo * fac, vhi = hi * fac;
    g_v2[idx] = pack2(vlo, vhi);
    if (out) {
        int sh = idx & 7;
        int b  = (idx >> 3) & (B - 1);
        int j  = idx >> 12;
        out[(b * J + j) * S + sh]     = vlo;
        out[(b * J + j) * S + sh + 8] = vhi;
    }
}

// ---------------------------------------------------------------------------
extern "C" void kernel_launch(void* const* d_in, const int* in_sizes, int n_in,
                              void* d_out, int out_size) {
    const float* x = (const float*)d_in[0];   // [512][8][1152]
    const float* W = (const float*)d_in[1];   // [1152][10][16][8]
    float* out = (float*)d_out;               // [512][10][16]

    cudaFuncSetAttribute(k_fused<0>, cudaFuncAttributeMaxDynamicSharedMemorySize,
                         (int)sizeof(SMem));
    cudaFuncSetAttribute(k_fused<1>, cudaFuncAttributeMaxDynamicSharedMemorySize,
                         (int)sizeof(SMem));

    k_transpose<<<dim3(C / 32, R / 32), dim3(32, 8)>>>(x);
    k_prepW<<<(C * J * 64 + 255) / 256, 256>>>(W);

    // t = 0: uniform cc = 1/J folded as postscale
    k_fused<0><<<NCB, NTHR, sizeof(SMem)>>>();
    k_rs1<<<dim3(J * B * 8 / 256, RSPLIT), 256>>>();
    k_rs2<<<J * B * 8 / 256, 256>>>(0.1f, nullptr);

    for (int t = 1; t < NR; t++) {
        k_fused<1><<<NCB, NTHR, sizeof(SMem)>>>();
        k_rs1<<<dim3(J * B * 8 / 256, RSPLIT), 256>>>();
        k_rs2<<<J * B * 8 / 256, 256>>>(1.f, t == NR - 1 ? out : nullptr);
    }
}

// round 5
// speedup vs baseline: 1.2135x; 1.2135x over previous
#include <cuda_runtime.h>
#include <math.h>

typedef unsigned long long ull;

// Problem constants
#define B    512
#define IU   8
#define C    1152
#define J    10
#define S    16
#define NR   3
#define R    (B*IU)      // 4096

// Tiling
#define CG   32          // c's per block group
#define NCG  (C/CG)      // 36 c-groups -> 36 partial groups
#define CCB  8           // c's per subchunk
#define NSUB (CG/CCB)    // 4
#define BT   128         // b's per block
#define NBT  (B/BT)      // 4
#define NTHR 512
#define WJS  72          // smem ull stride per (c,j) row (padded from 64)
#define WROW 64          // gmem ull per (c,j) row
#define WSUB (CCB*J*WJS) // 5760 ull
#define XSUB (CCB*BT*IU) // 8192 ull

// Scratch (__device__ globals; no allocation)
__device__ __align__(16) ull  g_xd[(size_t)C*R];        // duplicated x (x,x)  37.7MB
__device__ __align__(16) ull  g_Wp[(size_t)C*J*WROW];   // packed W (s,s+8)    5.9MB
__device__ float g_b[C*J];
__device__ float g_cc[C*J];
__device__ __align__(16) ull  g_sp2[NCG][(size_t)J*B*8];   // s partials 11.8MB
__device__ __align__(16) ull  g_spp[2][(size_t)J*B*8];     // split-k stage
__device__ __align__(16) ull  g_v2[(size_t)J*B*8];         // packed v
__device__ float g_bp[NBT][C*J];                            // delta_b partials

#define SMS_BYTES ((2*WSUB + 2*XSUB)*8 + CG*J*4)   // k_s: 224512 B
#define SMB_BYTES ((WSUB + 2*XSUB)*8 + 16*CCB*J*4) // k_b: 182272 B

// ---- packed f32x2 helpers ------------------------------------------------
__device__ __forceinline__ void fma2(ull& d, ull a, ull b) {
    asm("fma.rn.f32x2 %0, %1, %2, %0;" : "+l"(d) : "l"(a), "l"(b));
}
__device__ __forceinline__ ull add2(ull a, ull b) {
    ull d; asm("add.rn.f32x2 %0, %1, %2;" : "=l"(d) : "l"(a), "l"(b)); return d;
}
__device__ __forceinline__ ull pack2(float lo, float hi) {
    return ((ull)__float_as_uint(hi) << 32) | (ull)__float_as_uint(lo);
}
__device__ __forceinline__ ull dup2(float f) {
    unsigned u = __float_as_uint(f); return ((ull)u << 32) | (ull)u;
}
__device__ __forceinline__ float lo2(ull v) { return __uint_as_float((unsigned)v); }
__device__ __forceinline__ float hi2(ull v) { return __uint_as_float((unsigned)(v >> 32)); }

// ---- cp.async helpers ----------------------------------------------------
__device__ __forceinline__ void cpa16(void* dst, const void* src) {
    unsigned s = (unsigned)__cvta_generic_to_shared(dst);
    asm volatile("cp.async.cg.shared.global [%0], [%1], 16;" :: "r"(s), "l"(src));
}
__device__ __forceinline__ void cpcommit() {
    asm volatile("cp.async.commit_group;" ::: "memory");
}
template <int N> __device__ __forceinline__ void cpwait() {
    asm volatile("cp.async.wait_group %0;" :: "n"(N) : "memory");
}

// ---------------------------------------------------------------------------
// Prep: x[b][i][c] -> g_xd[c][b*8+i] duplicated (x,x)
// ---------------------------------------------------------------------------
__global__ void k_transpose(const float* __restrict__ x) {
    __shared__ float t[32][33];
    int cb = blockIdx.x * 32, rb = blockIdx.y * 32;
    int tx = threadIdx.x, ty = threadIdx.y;
    #pragma unroll
    for (int k = 0; k < 32; k += 8)
        t[ty + k][tx] = x[(size_t)(rb + ty + k) * C + cb + tx];
    __syncthreads();
    #pragma unroll
    for (int k = 0; k < 32; k += 8)
        g_xd[(size_t)(cb + ty + k) * R + rb + tx] = dup2(t[tx][ty + k]);
}

// Prep: W[c][j][s][i] -> g_Wp[cj][ih*32 + il*8 + sh] = (W[..sh..i], W[..sh+8..i])
__global__ void k_prepW(const float* __restrict__ W) {
    int gid = blockIdx.x * 256 + threadIdx.x;
    if (gid >= C * J * WROW) return;
    int sh = gid & 7, il = (gid >> 3) & 3, ih = (gid >> 5) & 1, cj = gid >> 6;
    int i = ih * 4 + il;
    float lo = W[((size_t)cj * 16 + sh) * 8 + i];
    float hi = W[((size_t)cj * 16 + sh + 8) * 8 + i];
    g_Wp[(size_t)cj * WROW + ih * 32 + il * 8 + sh] = pack2(lo, hi);
}

// ---------------------------------------------------------------------------
// cp.async stagers: W subchunk (2560 16B chunks), x subchunk (4096 chunks)
// ---------------------------------------------------------------------------
__device__ __forceinline__ void issue_W(ull* Wb, int cstart, int tid) {
    const ull* src = g_Wp + (size_t)cstart * J * WROW;
    #pragma unroll
    for (int t = tid; t < CCB * J * 32; t += NTHR) {
        int row = t >> 5, ch = t & 31;
        cpa16(Wb + row * WJS + ch * 2, src + row * WROW + ch * 2);
    }
}
__device__ __forceinline__ void issue_x(ull* xb, int cstart, int b0, int tid) {
    #pragma unroll
    for (int t = tid; t < CCB * BT * IU / 2; t += NTHR) {
        int cl = t >> 9, ch = t & 511;
        cpa16(xb + cl * (BT * IU) + ch * 2,
              g_xd + (size_t)(cstart + cl) * R + (size_t)b0 * IU + ch * 2);
    }
}

// ---------------------------------------------------------------------------
// K_s: partial s[j,b,s-pair] over this block's 32 c's. MODE 1: rescale the
// staged W subchunk in SMEM by cc before compute (keeps inner loop at the
// pure 8-fma2 floor). MODE 0: first iteration, cc uniform -> postscale later.
// ---------------------------------------------------------------------------
template <int MODE>
__global__ void __launch_bounds__(NTHR, 1) k_s() {
    extern __shared__ ull smu[];
    ull*   Wb2 = smu;                       // [2][WSUB]
    ull*   xb2 = smu + 2 * WSUB;            // [2][XSUB]
    float* ccs = (float*)(smu + 2 * WSUB + 2 * XSUB);  // [CG*J]
    int tid = threadIdx.x;
    int cg = blockIdx.x, bt = blockIdx.y;
    int c0 = cg * CG, b0 = bt * BT;
    int sh  = tid & 7;
    int jb  = ((tid >> 3) & 1) * 5;
    int bt4 = tid >> 4;

    if (MODE == 1)
        for (int t = tid; t < CG * J; t += NTHR)
            ccs[t] = __ldg(&g_cc[c0 * J + t]);

    issue_W(Wb2, c0, tid);
    issue_x(xb2, c0, b0, tid);
    cpcommit();

    ull acc[5][4];
    #pragma unroll
    for (int jj = 0; jj < 5; jj++)
        #pragma unroll
        for (int t = 0; t < 4; t++) acc[jj][t] = 0ull;

    for (int sc = 0; sc < NSUB; sc++) {
        if (sc > 0) __syncthreads();
        if (sc + 1 < NSUB) {
            issue_W(Wb2 + ((sc + 1) & 1) * WSUB, c0 + (sc + 1) * CCB, tid);
            issue_x(xb2 + ((sc + 1) & 1) * XSUB, c0 + (sc + 1) * CCB, b0, tid);
            cpcommit();
        }
        if (sc + 1 < NSUB) cpwait<1>(); else cpwait<0>();
        __syncthreads();
        ull* Wb = Wb2 + (sc & 1) * WSUB;
        const ull* xb = xb2 + (sc & 1) * XSUB;

        if (MODE == 1) {
            const float* cs = ccs + sc * CCB * J;
            #pragma unroll
            for (int t = tid; t < CCB * J * 64; t += NTHR) {
                int row = t >> 6;
                float cv = cs[row];
                ull w = Wb[row * WJS + (t & 63)];
                Wb[row * WJS + (t & 63)] = pack2(lo2(w) * cv, hi2(w) * cv);
            }
            __syncthreads();
        }

        #pragma unroll
        for (int cl = 0; cl < CCB; cl++) {
            const ull* xrow = xb + (cl * BT + bt4 * 4) * IU;
            #pragma unroll
            for (int ih = 0; ih < 2; ih++) {
                ulonglong2 xA[4], xB[4];
                #pragma unroll
                for (int t = 0; t < 4; t++) {
                    const ulonglong2* xp = (const ulonglong2*)(xrow + t * IU + ih * 4);
                    xA[t] = xp[0]; xB[t] = xp[1];
                }
                const ull* wb_ = Wb + (cl * J + jb) * WJS + ih * 32 + sh;
                #pragma unroll
                for (int jj = 0; jj < 5; jj++) {
                    const ull* w = wb_ + jj * WJS;
                    ull w0 = w[0], w1 = w[8], w2 = w[16], w3 = w[24];
                    #pragma unroll
                    for (int t = 0; t < 4; t++) {
                        fma2(acc[jj][t], w0, xA[t].x);
                        fma2(acc[jj][t], w1, xA[t].y);
                        fma2(acc[jj][t], w2, xB[t].x);
                        fma2(acc[jj][t], w3, xB[t].y);
                    }
                }
            }
        }
    }
    ull* spb = g_sp2[cg];
    #pragma unroll
    for (int jj = 0; jj < 5; jj++)
        #pragma unroll
        for (int t = 0; t < 4; t++)
            spb[((size_t)(jb + jj) * B + b0 + bt4 * 4 + t) * 8 + sh] = acc[jj][t];
}

// ---------------------------------------------------------------------------
// K_b: partial delta_b[c,j] = sum_{b in tile, s} v * u_hat. Raw W (no cc).
// Per subchunk: per-warp partials in dsm (deterministic), 80-thread reduce.
// ---------------------------------------------------------------------------
__global__ void __launch_bounds__(NTHR, 1) k_b() {
    extern __shared__ ull smu[];
    ull*   Wb  = smu;                       // [WSUB]
    ull*   xb2 = smu + WSUB;                // [2][XSUB]
    float* dsm = (float*)(smu + WSUB + 2 * XSUB);  // [16][CCB*J]
    int tid = threadIdx.x;
    int cg = blockIdx.x, bt = blockIdx.y;
    int c0 = cg * CG, b0 = bt * BT;
    int sh  = tid & 7;
    int jb  = ((tid >> 3) & 1) * 5;
    int bt4 = tid >> 4;
    int warp = tid >> 5, lane = tid & 31;

    issue_W(Wb, c0, tid);
    issue_x(xb2, c0, b0, tid);
    cpcommit();

    ull vv[5][4];
    #pragma unroll
    for (int jj = 0; jj < 5; jj++)
        #pragma unroll
        for (int t = 0; t < 4; t++)
            vv[jj][t] = g_v2[((size_t)(jb + jj) * B + b0 + bt4 * 4 + t) * 8 + sh];

    for (int sc = 0; sc < NSUB; sc++) {
        if (sc > 0) {
            __syncthreads();                 // protects Wb + dsm + x buffer reuse
            issue_W(Wb, c0 + sc * CCB, tid);
            cpcommit();
        }
        if (sc + 1 < NSUB) {
            issue_x(xb2 + ((sc + 1) & 1) * XSUB, c0 + (sc + 1) * CCB, b0, tid);
            cpcommit();
        }
        if (sc + 1 < NSUB) cpwait<1>(); else cpwait<0>();
        __syncthreads();
        const ull* xb = xb2 + (sc & 1) * XSUB;

        #pragma unroll 1
        for (int cl = 0; cl < CCB; cl++) {
            ull p2[5] = {0, 0, 0, 0, 0};
            const ull* xrow = xb + (cl * BT + bt4 * 4) * IU;
            #pragma unroll
            for (int ih = 0; ih < 2; ih++) {
                ulonglong2 xA[4], xB[4];
                #pragma unroll
                for (int t = 0; t < 4; t++) {
                    const ulonglong2* xp = (const ulonglong2*)(xrow + t * IU + ih * 4);
                    xA[t] = xp[0]; xB[t] = xp[1];
                }
                const ull* wb_ = Wb + (cl * J + jb) * WJS + ih * 32 + sh;
                #pragma unroll
                for (int jj = 0; jj < 5; jj++) {
                    const ull* w = wb_ + jj * WJS;
                    ull y0 = 0, y1 = 0, y2 = 0, y3 = 0;
                    #pragma unroll
                    for (int t = 0; t < 4; t++) {
                        fma2(y0, vv[jj][t], xA[t].x);
                        fma2(y1, vv[jj][t], xA[t].y);
                        fma2(y2, vv[jj][t], xB[t].x);
                        fma2(y3, vv[jj][t], xB[t].y);
                    }
                    fma2(p2[jj], w[0],  y0);
                    fma2(p2[jj], w[8],  y1);
                    fma2(p2[jj], w[16], y2);
                    fma2(p2[jj], w[24], y3);
                }
            }
            #pragma unroll
            for (int jj = 0; jj < 5; jj++) {
                float p = lo2(p2[jj]) + hi2(p2[jj]);
                p += __shfl_xor_sync(0xffffffffu, p, 1);
                p += __shfl_xor_sync(0xffffffffu, p, 2);
                p += __shfl_xor_sync(0xffffffffu, p, 4);
                p += __shfl_xor_sync(0xffffffffu, p, 16);
                if ((lane & 23) == 0)   // lanes 0 (jg0) and 8 (jg1)
                    dsm[warp * (CCB * J) + cl * J + jb + jj] = p;
            }
        }
        __syncthreads();
        if (tid < CCB * J) {
            float s = 0.f;
            #pragma unroll
            for (int w = 0; w < 16; w++) s += dsm[w * (CCB * J) + tid];
            g_bp[bt][(c0 + sc * CCB + tid / J) * J + tid % J] = s;
        }
    }
}

// ---------------------------------------------------------------------------
// b update (+implicit zero base on first call) + softmax over j per c.
// ---------------------------------------------------------------------------
__global__ void k_softmax(int first) {
    int c = blockIdx.x * 128 + threadIdx.x;
    if (c >= C) return;
    float bv[J];
    #pragma unroll
    for (int j = 0; j < J; j++) {
        float base = first ? 0.f : g_b[c * J + j];
        float d = 0.f;
        #pragma unroll
        for (int p = 0; p < NBT; p++) d += g_bp[p][c * J + j];
        float nb = base + d * (1.f / B);
        g_b[c * J + j] = nb;
        bv[j] = nb;
    }
    float m = bv[0];
    #pragma unroll
    for (int j = 1; j < J; j++) m = fmaxf(m, bv[j]);
    float su = 0.f;
    #pragma unroll
    for (int j = 0; j < J; j++) { bv[j] = expf(bv[j] - m); su += bv[j]; }
    float inv = 1.f / su;
    #pragma unroll
    for (int j = 0; j < J; j++) g_cc[c * J + j] = bv[j] * inv;
}

// ---------------------------------------------------------------------------
// Split-2 reduction of 36 partials, then squash.
// ---------------------------------------------------------------------------
__global__ void k_rs1() {
    int idx = blockIdx.x * 256 + threadIdx.x;
    int p0 = blockIdx.y * (NCG / 2);
    ull a0 = 0ull, a1 = 0ull;
    #pragma unroll
    for (int p = 0; p < NCG / 2; p += 2) {
        a0 = add2(a0, g_sp2[p0 + p][idx]);
        a1 = add2(a1, g_sp2[p0 + p + 1][idx]);
    }
    g_spp[blockIdx.y][idx] = add2(a0, a1);
}

__global__ void k_rs2(float postscale, float* __restrict__ out) {
    int idx = blockIdx.x * 256 + threadIdx.x;
    ull a = add2(g_spp[0][idx], g_spp[1][idx]);
    float lo = lo2(a) * postscale;
    float hi = hi2(a) * postscale;
    float m = lo * lo + hi * hi;
    m += __shfl_xor_sync(0xffffffffu, m, 1);
    m += __shfl_xor_sync(0xffffffffu, m, 2);
    m += __shfl_xor_sync(0xffffffffu, m, 4);
    float fac = sqrtf(m) / (1.f + m);
    float vlo = lo * fac, vhi = hi * fac;
    g_v2[idx] = pack2(vlo, vhi);
    if (out) {
        int sh = idx & 7;
        int b  = (idx >> 3) & (B - 1);
        int j  = idx >> 12;
        out[(b * J + j) * S + sh]     = vlo;
        out[(b * J + j) * S + sh + 8] = vhi;
    }
}

// ---------------------------------------------------------------------------
extern "C" void kernel_launch(void* const* d_in, const int* in_sizes, int n_in,
                              void* d_out, int out_size) {
    const float* x = (const float*)d_in[0];   // [512][8][1152]
    const float* W = (const float*)d_in[1];   // [1152][10][16][8]
    float* out = (float*)d_out;               // [512][10][16]

    cudaFuncSetAttribute(k_s<0>, cudaFuncAttributeMaxDynamicSharedMemorySize, SMS_BYTES);
    cudaFuncSetAttribute(k_s<1>, cudaFuncAttributeMaxDynamicSharedMemorySize, SMS_BYTES);
    cudaFuncSetAttribute(k_b,    cudaFuncAttributeMaxDynamicSharedMemorySize, SMB_BYTES);

    k_transpose<<<dim3(C / 32, R / 32), dim3(32, 8)>>>(x);
    k_prepW<<<(C * J * WROW + 255) / 256, 256>>>(W);

    dim3 grid(NCG, NBT);
    // t = 0: uniform cc = 1/J folded as postscale
    k_s<0><<<grid, NTHR, SMS_BYTES>>>();
    k_rs1<<<dim3(J * B * 8 / 256, 2), 256>>>();
    k_rs2<<<J * B * 8 / 256, 256>>>(0.1f, nullptr);

    for (int t = 1; t < NR; t++) {
        k_b<<<grid, NTHR, SMB_BYTES>>>();
        k_softmax<<<(C + 127) / 128, 128>>>(t == 1 ? 1 : 0);
        k_s<1><<<grid, NTHR, SMS_BYTES>>>();
        k_rs1<<<dim3(J * B * 8 / 256, 2), 256>>>();
        k_rs2<<<J * B * 8 / 256, 256>>>(1.f, t == NR - 1 ? out : nullptr);
    }
}

// round 9
// speedup vs baseline: 1.3696x; 1.1286x over previous
#include <cuda_runtime.h>
#include <math.h>

typedef unsigned long long ull;

// Problem constants
#define B    512
#define IU   8
#define C    1152
#define J    10
#define S    16
#define NR   3
#define R    (B*IU)      // 4096

// Tiling
#define CG   32          // c's per block group
#define NCG  (C/CG)      // 36 c-groups -> 36 partial groups
#define CCB  8           // c's per subchunk
#define NSUB (CG/CCB)    // 4
#define BT   128         // b's per block
#define NBT  (B/BT)      // 4
#define NTHR 512
#define WJS  72          // smem ull stride per (c,j) row (padded from 64)
#define WROW 64          // gmem ull per (c,j) row
#define WSUB (CCB*J*WJS) // 5760 ull
#define XSUBF (CCB*BT*IU) // 8192 floats per x subchunk (UNduplicated)
#define RSP  4           // k_rs1 split factor (36 = 4*9)

// Scratch (__device__ globals; no allocation)
__device__ __align__(16) float g_xT[(size_t)C*R];       // plain x [c][b*8+i] 18.9MB
__device__ __align__(16) ull  g_Wp[(size_t)C*J*WROW];   // packed W (s,s+8)   5.9MB
__device__ float g_bA[C*J];                              // b after iter 1
__device__ float g_bB[C*J];                              // b after iter 2 (unused read)
__device__ __align__(16) ull  g_sp2[NCG][(size_t)J*B*8];   // s partials 11.8MB
__device__ __align__(16) ull  g_spp[RSP][(size_t)J*B*8];   // split-k stage
__device__ __align__(16) ull  g_v2[(size_t)J*B*8];         // packed v
__device__ float g_bp[NBT][C*J];                            // delta_b partials

// SMEM layouts
struct SMemS {
    ull   Wp[2][WSUB];       // 92160 B
    float xf[2][XSUBF];      // 65536 B
    float ccs[CG*J];         // 1280 B
    float bn[CG*J];          // 1280 B
};
struct SMemB {
    ull   Wp[WSUB];          // 46080 B
    float xf[2][XSUBF];      // 65536 B
    float dsm[16*CCB*J];     // 5120 B
};

// ---- packed f32x2 helpers ------------------------------------------------
__device__ __forceinline__ void fma2(ull& d, ull a, ull b) {
    asm("fma.rn.f32x2 %0, %1, %2, %0;" : "+l"(d) : "l"(a), "l"(b));
}
__device__ __forceinline__ ull add2(ull a, ull b) {
    ull d; asm("add.rn.f32x2 %0, %1, %2;" : "=l"(d) : "l"(a), "l"(b)); return d;
}
__device__ __forceinline__ ull pack2(float lo, float hi) {
    return ((ull)__float_as_uint(hi) << 32) | (ull)__float_as_uint(lo);
}
__device__ __forceinline__ ull dup2(float f) {
    unsigned u = __float_as_uint(f); return ((ull)u << 32) | (ull)u;
}
__device__ __forceinline__ float lo2(ull v) { return __uint_as_float((unsigned)v); }
__device__ __forceinline__ float hi2(ull v) { return __uint_as_float((unsigned)(v >> 32)); }

// ---- cp.async helpers ----------------------------------------------------
__device__ __forceinline__ void cpa16(void* dst, const void* src) {
    unsigned s = (unsigned)__cvta_generic_to_shared(dst);
    asm volatile("cp.async.cg.shared.global [%0], [%1], 16;" :: "r"(s), "l"(src));
}
__device__ __forceinline__ void cpcommit() {
    asm volatile("cp.async.commit_group;" ::: "memory");
}
template <int N> __device__ __forceinline__ void cpwait() {
    asm volatile("cp.async.wait_group %0;" :: "n"(N) : "memory");
}

// ---------------------------------------------------------------------------
// Prep: x[b][i][c] -> g_xT[c][b*8+i] (plain float)
// ---------------------------------------------------------------------------
__global__ void k_transpose(const float* __restrict__ x) {
    __shared__ float t[32][33];
    int cb = blockIdx.x * 32, rb = blockIdx.y * 32;
    int tx = threadIdx.x, ty = threadIdx.y;
    #pragma unroll
    for (int k = 0; k < 32; k += 8)
        t[ty + k][tx] = x[(size_t)(rb + ty + k) * C + cb + tx];
    __syncthreads();
    #pragma unroll
    for (int k = 0; k < 32; k += 8)
        g_xT[(size_t)(cb + ty + k) * R + rb + tx] = t[tx][ty + k];
}

// Prep: W[c][j][s][i] -> g_Wp[cj][ih*32 + il*8 + sh] = (W[..sh..i], W[..sh+8..i])
__global__ void k_prepW(const float* __restrict__ W) {
    int gid = blockIdx.x * 256 + threadIdx.x;
    if (gid >= C * J * WROW) return;
    int sh = gid & 7, il = (gid >> 3) & 3, ih = (gid >> 5) & 1, cj = gid >> 6;
    int i = ih * 4 + il;
    float lo = W[((size_t)cj * 16 + sh) * 8 + i];
    float hi = W[((size_t)cj * 16 + sh + 8) * 8 + i];
    g_Wp[(size_t)cj * WROW + ih * 32 + il * 8 + sh] = pack2(lo, hi);
}

// ---------------------------------------------------------------------------
// cp.async stagers
// ---------------------------------------------------------------------------
__device__ __forceinline__ void issue_W(ull* Wb, int cstart, int tid) {
    const ull* src = g_Wp + (size_t)cstart * J * WROW;
    #pragma unroll
    for (int t = tid; t < CCB * J * 32; t += NTHR) {
        int row = t >> 5, ch = t & 31;
        cpa16(Wb + row * WJS + ch * 2, src + row * WROW + ch * 2);
    }
}
// x: 8192 floats = 2048 16B-chunks per subchunk (UNduplicated)
__device__ __forceinline__ void issue_x(float* xb, int cstart, int b0, int tid) {
    #pragma unroll
    for (int t = tid; t < XSUBF / 4; t += NTHR) {
        int cl = t >> 8, ch = t & 255;   // 256 chunks per c (128b*8i*4B/16)
        cpa16(xb + cl * (BT * IU) + ch * 4,
              g_xT + (size_t)(cstart + cl) * R + (size_t)b0 * IU + ch * 4);
    }
}

// ---------------------------------------------------------------------------
// K_s: partial s[j,b,(s,s+8)] over this block's 32 c's.
// MODE 1: recompute b-update + softmax in-block (from g_bp), rescale staged W
// in SMEM by cc. EPOCH selects the b ping-pong buffer.
// MODE 0: first iteration, uniform cc folded as 0.1 postscale in k_rs2.
// ---------------------------------------------------------------------------
template <int MODE, int EPOCH>
__global__ void __launch_bounds__(NTHR, 1) k_s() {
    extern __shared__ char smraw[];
    SMemS& sm = *(SMemS*)smraw;
    int tid = threadIdx.x;
    int cg = blockIdx.x, bt = blockIdx.y;
    int c0 = cg * CG, b0 = bt * BT;
    int sh  = tid & 7;
    int jb  = ((tid >> 3) & 1) * 5;
    int bt4 = tid >> 4;

    issue_W(sm.Wp[0], c0, tid);
    issue_x(sm.xf[0], c0, b0, tid);
    cpcommit();

    if (MODE == 1) {
        // b update + softmax for this block's 32 c's (deterministic,
        // identical across the 4 bt blocks; only bt==0 persists b).
        if (tid < CG * J) {
            int j = tid % J, c = c0 + tid / J;
            float d = g_bp[0][c * J + j] + g_bp[1][c * J + j]
                    + g_bp[2][c * J + j] + g_bp[3][c * J + j];
            float nb = d * (1.f / B);
            if (EPOCH == 1) nb += g_bA[c * J + j];
            sm.bn[tid] = nb;
            if (bt == 0) {
                if (EPOCH == 0) g_bA[c * J + j] = nb;
                else            g_bB[c * J + j] = nb;
            }
        }
        __syncthreads();
        if (tid < CG * J) {
            int cl = tid / J;
            float mx = sm.bn[cl * J];
            #pragma unroll
            for (int q = 1; q < J; q++) mx = fmaxf(mx, sm.bn[cl * J + q]);
            float su = 0.f;
            #pragma unroll
            for (int q = 0; q < J; q++) su += expf(sm.bn[cl * J + q] - mx);
            sm.ccs[tid] = expf(sm.bn[tid] - mx) / su;
        }
        // loop's post-wait __syncthreads orders ccs before first rescale read
    }

    ull acc[5][4];
    #pragma unroll
    for (int jj = 0; jj < 5; jj++)
        #pragma unroll
        for (int t = 0; t < 4; t++) acc[jj][t] = 0ull;

    for (int sc = 0; sc < NSUB; sc++) {
        if (sc > 0) __syncthreads();
        if (sc + 1 < NSUB) {
            issue_W(sm.Wp[(sc + 1) & 1], c0 + (sc + 1) * CCB, tid);
            issue_x(sm.xf[(sc + 1) & 1], c0 + (sc + 1) * CCB, b0, tid);
            cpcommit();
        }
        if (sc + 1 < NSUB) cpwait<1>(); else cpwait<0>();
        __syncthreads();
        ull* Wb = sm.Wp[sc & 1];
        const float* xb = sm.xf[sc & 1];

        if (MODE == 1) {
            const float* cs = sm.ccs + sc * CCB * J;
            #pragma unroll
            for (int t = tid; t < CCB * J * 64; t += NTHR) {
                int row = t >> 6;
                float cv = cs[row];
                ull w = Wb[row * WJS + (t & 63)];
                Wb[row * WJS + (t & 63)] = pack2(lo2(w) * cv, hi2(w) * cv);
            }
            __syncthreads();
        }

        #pragma unroll
        for (int cl = 0; cl < CCB; cl++) {
            const float* xrow = xb + (cl * BT + bt4 * 4) * IU;
            #pragma unroll
            for (int ih = 0; ih < 2; ih++) {
                ull xd_[4][4];
                #pragma unroll
                for (int t = 0; t < 4; t++) {
                    float4 xf4 = *(const float4*)(xrow + t * IU + ih * 4);
                    xd_[t][0] = dup2(xf4.x);
                    xd_[t][1] = dup2(xf4.y);
                    xd_[t][2] = dup2(xf4.z);
                    xd_[t][3] = dup2(xf4.w);
                }
                const ull* wb_ = Wb + (cl * J + jb) * WJS + ih * 32 + sh;
                #pragma unroll
                for (int jj = 0; jj < 5; jj++) {
                    const ull* w = wb_ + jj * WJS;
                    ull w0 = w[0], w1 = w[8], w2 = w[16], w3 = w[24];
                    #pragma unroll
                    for (int t = 0; t < 4; t++) {
                        fma2(acc[jj][t], w0, xd_[t][0]);
                        fma2(acc[jj][t], w1, xd_[t][1]);
                        fma2(acc[jj][t], w2, xd_[t][2]);
                        fma2(acc[jj][t], w3, xd_[t][3]);
                    }
                }
            }
        }
    }
    ull* spb = g_sp2[cg];
    #pragma unroll
    for (int jj = 0; jj < 5; jj++)
        #pragma unroll
        for (int t = 0; t < 4; t++)
            spb[((size_t)(jb + jj) * B + b0 + bt4 * 4 + t) * 8 + sh] = acc[jj][t];
}

// ---------------------------------------------------------------------------
// K_b: partial delta_b[c,j] = sum_{b in tile, s} v * u_hat. Raw W (no cc).
// ---------------------------------------------------------------------------
__global__ void __launch_bounds__(NTHR, 1) k_b() {
    extern __shared__ char smraw[];
    SMemB& sm = *(SMemB*)smraw;
    int tid = threadIdx.x;
    int cg = blockIdx.x, bt = blockIdx.y;
    int c0 = cg * CG, b0 = bt * BT;
    int sh  = tid & 7;
    int jb  = ((tid >> 3) & 1) * 5;
    int bt4 = tid >> 4;
    int warp = tid >> 5, lane = tid & 31;

    issue_W(sm.Wp, c0, tid);
    issue_x(sm.xf[0], c0, b0, tid);
    cpcommit();

    ull vv[5][4];
    #pragma unroll
    for (int jj = 0; jj < 5; jj++)
        #pragma unroll
        for (int t = 0; t < 4; t++)
            vv[jj][t] = g_v2[((size_t)(jb + jj) * B + b0 + bt4 * 4 + t) * 8 + sh];

    for (int sc = 0; sc < NSUB; sc++) {
        if (sc > 0) {
            __syncthreads();                 // protects Wp + dsm + x buffer reuse
            issue_W(sm.Wp, c0 + sc * CCB, tid);
            cpcommit();
        }
        if (sc + 1 < NSUB) {
            issue_x(sm.xf[(sc + 1) & 1], c0 + (sc + 1) * CCB, b0, tid);
            cpcommit();
        }
        if (sc + 1 < NSUB) cpwait<1>(); else cpwait<0>();
        __syncthreads();
        const float* xb = sm.xf[sc & 1];

        #pragma unroll 1
        for (int cl = 0; cl < CCB; cl++) {
            ull p2[5] = {0, 0, 0, 0, 0};
            const float* xrow = xb + (cl * BT + bt4 * 4) * IU;
            #pragma unroll
            for (int ih = 0; ih < 2; ih++) {
                ull xd_[4][4];
                #pragma unroll
                for (int t = 0; t < 4; t++) {
                    float4 xf4 = *(const float4*)(xrow + t * IU + ih * 4);
                    xd_[t][0] = dup2(xf4.x);
                    xd_[t][1] = dup2(xf4.y);
                    xd_[t][2] = dup2(xf4.z);
                    xd_[t][3] = dup2(xf4.w);
                }
                const ull* wb_ = sm.Wp + (cl * J + jb) * WJS + ih * 32 + sh;
                #pragma unroll
                for (int jj = 0; jj < 5; jj++) {
                    const ull* w = wb_ + jj * WJS;
                    ull y0 = 0, y1 = 0, y2 = 0, y3 = 0;
                    #pragma unroll
                    for (int t = 0; t < 4; t++) {
                        fma2(y0, vv[jj][t], xd_[t][0]);
                        fma2(y1, vv[jj][t], xd_[t][1]);
                        fma2(y2, vv[jj][t], xd_[t][2]);
                        fma2(y3, vv[jj][t], xd_[t][3]);
                    }
                    fma2(p2[jj], w[0],  y0);
                    fma2(p2[jj], w[8],  y1);
                    fma2(p2[jj], w[16], y2);
                    fma2(p2[jj], w[24], y3);
                }
            }
            #pragma unroll
            for (int jj = 0; jj < 5; jj++) {
                float p = lo2(p2[jj]) + hi2(p2[jj]);
                p += __shfl_xor_sync(0xffffffffu, p, 1);
                p += __shfl_xor_sync(0xffffffffu, p, 2);
                p += __shfl_xor_sync(0xffffffffu, p, 4);
                p += __shfl_xor_sync(0xffffffffu, p, 16);
                if ((lane & 23) == 0)   // lanes 0 (jg0) and 8 (jg1)
                    sm.dsm[warp * (CCB * J) + cl * J + jb + jj] = p;
            }
        }
        __syncthreads();
        if (tid < CCB * J) {
            float s = 0.f;
            #pragma unroll
            for (int w = 0; w < 16; w++) s += sm.dsm[w * (CCB * J) + tid];
            g_bp[bt][(c0 + sc * CCB + tid / J) * J + tid % J] = s;
        }
    }
}

// ---------------------------------------------------------------------------
// Split-4 reduction of 36 partials, then squash.
// ---------------------------------------------------------------------------
__global__ void k_rs1() {
    int idx = blockIdx.x * 256 + threadIdx.x;   // [0, 40960)
    int p0 = blockIdx.y * (NCG / RSP);          // 9 each
    ull a0 = 0ull, a1 = 0ull, a2 = 0ull;
    #pragma unroll
    for (int p = 0; p < NCG / RSP; p += 3) {
        a0 = add2(a0, g_sp2[p0 + p][idx]);
        a1 = add2(a1, g_sp2[p0 + p + 1][idx]);
        a2 = add2(a2, g_sp2[p0 + p + 2][idx]);
    }
    g_spp[blockIdx.y][idx] = add2(a0, add2(a1, a2));
}

__global__ void k_rs2(float postscale, float* __restrict__ out) {
    int idx = blockIdx.x * 256 + threadIdx.x;
    ull a = add2(add2(g_spp[0][idx], g_spp[1][idx]),
                 add2(g_spp[2][idx], g_spp[3][idx]));
    float lo = lo2(a) * postscale;
    float hi = hi2(a) * postscale;
    float m = lo * lo + hi * hi;
    m += __shfl_xor_sync(0xffffffffu, m, 1);
    m += __shfl_xor_sync(0xffffffffu, m, 2);
    m += __shfl_xor_sync(0xffffffffu, m, 4);
    float fac = sqrtf(m) / (1.f + m);
    float vlo = lo * fac, vhi = hi * fac;
    g_v2[idx] = pack2(vlo, vhi);
    if (out) {
        int sh = idx & 7;
        int b  = (idx >> 3) & (B - 1);
        int j  = idx >> 12;
        out[(b * J + j) * S + sh]     = vlo;
        out[(b * J + j) * S + sh + 8] = vhi;
    }
}

// ---------------------------------------------------------------------------
extern "C" void kernel_launch(void* const* d_in, const int* in_sizes, int n_in,
                              void* d_out, int out_size) {
    const float* x = (const float*)d_in[0];   // [512][8][1152]
    const float* W = (const float*)d_in[1];   // [1152][10][16][8]
    float* out = (float*)d_out;               // [512][10][16]

    cudaFuncSetAttribute(k_s<0,0>, cudaFuncAttributeMaxDynamicSharedMemorySize,
                         (int)sizeof(SMemS));
    cudaFuncSetAttribute(k_s<1,0>, cudaFuncAttributeMaxDynamicSharedMemorySize,
                         (int)sizeof(SMemS));
    cudaFuncSetAttribute(k_s<1,1>, cudaFuncAttributeMaxDynamicSharedMemorySize,
                         (int)sizeof(SMemS));
    cudaFuncSetAttribute(k_b, cudaFuncAttributeMaxDynamicSharedMemorySize,
                         (int)sizeof(SMemB));

    k_transpose<<<dim3(C / 32, R / 32), dim3(32, 8)>>>(x);
    k_prepW<<<(C * J * WROW + 255) / 256, 256>>>(W);

    dim3 grid(NCG, NBT);
    dim3 rgrid(J * B * 8 / 256, RSP);

    // t = 0: uniform cc = 1/J folded as postscale
    k_s<0,0><<<grid, NTHR, sizeof(SMemS)>>>();
    k_rs1<<<rgrid, 256>>>();
    k_rs2<<<J * B * 8 / 256, 256>>>(0.1f, nullptr);

    // t = 1
    k_b<<<grid, NTHR, sizeof(SMemB)>>>();
    k_s<1,0><<<grid, NTHR, sizeof(SMemS)>>>();
    k_rs1<<<rgrid, 256>>>();
    k_rs2<<<J * B * 8 / 256, 256>>>(1.f, nullptr);

    // t = 2
    k_b<<<grid, NTHR, sizeof(SMemB)>>>();
    k_s<1,1><<<grid, NTHR, sizeof(SMemS)>>>();
    k_rs1<<<rgrid, 256>>>();
    k_rs2<<<J * B * 8 / 256, 256>>>(1.f, out);
}